// round 16
// baseline (speedup 1.0000x reference)
#include <cuda_runtime.h>
#include <cuda_bf16.h>

// MPS contraction (R11 structure; prq re-balanced for 3 blocks/SM):
//   prq_kernel : tensor -> pair matrices -> quad combos R (smem) ->
//                per-batch quad matrices Q (bf16, packed f32x2 FMA,
//                coefficients staged in smem, acc split into 2-batch passes).
//   chain_kernel: boundary-vector chains in packed bf16 (HFMA2), smem
//                 ping-pong v broadcast, depth-8 register prefetch.
//                 (exact R11/R8 best-measured version)
// N=1024 sites, B=256, D=16, d=2, C=10.

#define NQUAD 256          // quads 0..127 left, 128..255 right (stored transposed)
#define B_DIM 256
#define C_DIM 10

// g_Qh: bf16, index b*65536 + q*256 + j*16 + k  (column j of quad q, k pairs
// packed (k even = low half) by cvt_bf16x2)
__device__ __nv_bfloat16 g_Qh[(size_t)B_DIM * NQUAD * 256]; // 32 MB

// ---- packed helpers --------------------------------------------------------
__device__ __forceinline__ unsigned long long pack2(float lo, float hi) {
    unsigned long long r;
    asm("mov.b64 %0, {%1, %2};" : "=l"(r) : "f"(lo), "f"(hi));
    return r;
}
__device__ __forceinline__ void fma2(unsigned long long& d,
                                     unsigned long long a, unsigned long long b) {
    asm("fma.rn.f32x2 %0, %1, %2, %0;" : "+l"(d) : "l"(a), "l"(b));
}
// u64 (lo = k even, hi = k odd) -> bf16x2 word with k-even in low half
__device__ __forceinline__ unsigned cvt_bf16x2(unsigned long long v) {
    float lo, hi; unsigned p;
    asm("mov.b64 {%0, %1}, %2;" : "=f"(lo), "=f"(hi) : "l"(v));
    asm("cvt.rn.satfinite.bf16x2.f32 %0, %1, %2;" : "=r"(p) : "f"(hi), "f"(lo));
    return p;
}
__device__ __forceinline__ unsigned hmul2(unsigned a, unsigned b) {
    unsigned r;
    asm("mul.rn.bf16x2 %0, %1, %2;" : "=r"(r) : "r"(a), "r"(b));
    return r;
}
__device__ __forceinline__ void hfma2(unsigned& d, unsigned a, unsigned b) {
    asm("fma.rn.bf16x2 %0, %1, %2, %0;" : "+r"(d) : "r"(a), "r"(b));
}
__device__ __forceinline__ unsigned hadd2(unsigned a, unsigned b) {
    unsigned r;
    asm("add.rn.bf16x2 %0, %1, %2;" : "=r"(r) : "r"(a), "r"(b));
    return r;
}

// ---------------------------------------------------------------------------
// K1 (fused): one block per quad q (sites 4q..4q+3), 256 threads, 3 blocks/SM.
// Stage A/B identical to R11. Stage C: 4 slices x 64 batches; within a slice
// TWO passes of 2 batches each (acc[2][8] = 32 regs instead of 64), csh
// reused across passes with no extra barriers.
// ---------------------------------------------------------------------------
__global__ __launch_bounds__(256, 3)
void prq_kernel(const float* __restrict__ tensor, const float* __restrict__ x)
{
    __shared__ float T[4][1024];                 // 16 KB  [site][l*32 + r*2 + dd]
    __shared__ float SA[4][16 * 17], SB[4][16 * 17];   // 8.5 KB
    __shared__ float Rsh[16 * 288];              // 18 KB, [g][j*18 + k]
    __shared__ float csh[64 * 16];               // 4 KB,  [bl][g]

    // xs aliases T (dead after stage A): [site][batch] float2, 8 KB
    float2* xs = (float2*)&T[0][0];

    const int q = blockIdx.x;
    const int t = threadIdx.x;

    // ---- Stage A: load 4 sites, compute pair matrices ----
    {
        const float4* src = (const float4*)(tensor + (size_t)q * 4096);
        float4* dst = (float4*)&T[0][0];
#pragma unroll
        for (int i = 0; i < 4; i++) dst[t + 256 * i] = src[t + 256 * i];
    }
    __syncthreads();

    const int l = t >> 4;
    const int r = t & 15;
    float pa[4] = {0.f, 0.f, 0.f, 0.f};
    float pb[4] = {0.f, 0.f, 0.f, 0.f};
#pragma unroll
    for (int k = 0; k < 16; k++) {
        const float2 a0 = *(const float2*)&T[0][l * 32 + k * 2];
        const float2 a1 = *(const float2*)&T[1][k * 32 + r * 2];
        pa[0] = fmaf(a0.x, a1.x, pa[0]);
        pa[1] = fmaf(a0.x, a1.y, pa[1]);
        pa[2] = fmaf(a0.y, a1.x, pa[2]);
        pa[3] = fmaf(a0.y, a1.y, pa[3]);
        const float2 b0 = *(const float2*)&T[2][l * 32 + k * 2];
        const float2 b1 = *(const float2*)&T[3][k * 32 + r * 2];
        pb[0] = fmaf(b0.x, b1.x, pb[0]);
        pb[1] = fmaf(b0.x, b1.y, pb[1]);
        pb[2] = fmaf(b0.y, b1.x, pb[2]);
        pb[3] = fmaf(b0.y, b1.y, pb[3]);
    }
    __syncthreads();   // all T reads complete; T becomes xs storage below

    const int idx = (q < 128) ? (l * 17 + r) : (r * 17 + l);   // transpose right side
#pragma unroll
    for (int e = 0; e < 4; e++) { SA[e][idx] = pa[e]; SB[e][idx] = pb[e]; }

    // stage x for ALL 256 batches: 4 sites x 256 batches float2, coalesced
#pragma unroll
    for (int i = 0; i < 4; i++) {
        const int id = t + 256 * i;
        const int s  = id >> 8;
        const int bb = id & 255;
        xs[id] = ((const float2*)x)[(size_t)(4 * q + s) * 256 + bb];
    }
    __syncthreads();

    // ---- Stage B: R columns into padded smem ----
    {
        const int g  = t >> 4;     // combo e*4+f
        const int jj = t & 15;     // output column
        const int e = g >> 2, f = g & 3;
        const float* P1 = (q < 128) ? SA[e] : SB[f];
        const float* P2 = (q < 128) ? SB[f] : SA[e];

        float acc[16];
#pragma unroll
        for (int k = 0; k < 16; k++) acc[k] = 0.f;
#pragma unroll
        for (int m = 0; m < 16; m++) {
            const float bsc = P2[m * 17 + jj];
#pragma unroll
            for (int k = 0; k < 16; k++)
                acc[k] = fmaf(P1[k * 17 + m], bsc, acc[k]);
        }
        float2* dst = (float2*)&Rsh[g * 288 + jj * 18];
#pragma unroll
        for (int kp = 0; kp < 8; kp++)
            dst[kp] = make_float2(acc[2 * kp], acc[2 * kp + 1]);
    }
    __syncthreads();

    // ---- Stage C: 4 slices of 64 batches; two 2-batch passes per slice ----
    const int bg = t >> 4;      // 16 groups of 4 batches
    const int j  = t & 15;

#pragma unroll 1
    for (int s8 = 0; s8 < 4; s8++) {
        // compute csh[bl][g]: thread (e = t>>6, bl = t&63) fills g = e*4 + 0..3
        {
            const int bl = t & 63;
            const int e  = t >> 6;
            const float2 x0 = xs[0 * 256 + s8 * 64 + bl];
            const float2 x1 = xs[1 * 256 + s8 * 64 + bl];
            const float2 x2 = xs[2 * 256 + s8 * 64 + bl];
            const float2 x3 = xs[3 * 256 + s8 * 64 + bl];
            const float cAe = ((e >> 1) ? x0.y : x0.x) * ((e & 1) ? x1.y : x1.x);
            float4* cd = (float4*)&csh[bl * 16 + e * 4];
            *cd = make_float4(cAe * (x2.x * x3.x), cAe * (x2.x * x3.y),
                              cAe * (x2.y * x3.x), cAe * (x2.y * x3.y));
        }
        __syncthreads();

#pragma unroll 1
        for (int half = 0; half < 2; half++) {
            const int blb = bg * 4 + half * 2;          // local batch base
            const int b0  = s8 * 64 + blb;

            unsigned long long acc[2][8];
#pragma unroll
            for (int bb = 0; bb < 2; bb++)
#pragma unroll
                for (int kp = 0; kp < 8; kp++) acc[bb][kp] = 0ull;

#pragma unroll
            for (int g = 0; g < 16; g++) {
                const float c0s = csh[(blb + 0) * 16 + g];
                const float c1s = csh[(blb + 1) * 16 + g];
                const unsigned long long c0 = pack2(c0s, c0s);
                const unsigned long long c1 = pack2(c1s, c1s);
                const unsigned long long* Rp =
                    (const unsigned long long*)&Rsh[g * 288 + j * 18];
#pragma unroll
                for (int kp = 0; kp < 8; kp++) {
                    const unsigned long long rr = Rp[kp];   // conflict-free LDS.64
                    fma2(acc[0][kp], c0, rr);
                    fma2(acc[1][kp], c1, rr);
                }
            }

#pragma unroll
            for (int bb = 0; bb < 2; bb++) {
                unsigned w[8];
#pragma unroll
                for (int kp = 0; kp < 8; kp++) w[kp] = cvt_bf16x2(acc[bb][kp]);
                uint4* dst = (uint4*)(g_Qh + (size_t)(b0 + bb) * 65536 + q * 256 + j * 16);
                dst[0] = make_uint4(w[0], w[1], w[2], w[3]);
                dst[1] = make_uint4(w[4], w[5], w[6], w[7]);
            }
        }
        __syncthreads();   // csh reuse by next slice
    }
}

// ---------------------------------------------------------------------------
// K2: chains in packed bf16 (exact R11/R8 best version). grid=256 single-warp
// blocks (one batch each); lanes 0-15 left chain (q ascending), lanes 16-31
// right chain (q descending, transposed quads). Depth-8 register prefetch
// with compile-time slot indices. Per step: 2 LDS.128 (packed v) + 8 HFMA2 +
// 2 HADD2 + PRMT + STS.16 + syncwarp.
// ---------------------------------------------------------------------------
__global__ __launch_bounds__(32)
void chain_kernel(const float* __restrict__ Aout, float* __restrict__ out)
{
    __shared__ uint4 vsmv[2][2][2];   // [pingpong][half][2] = 16 bf16 per half

    const int b    = blockIdx.x;
    const int lane = threadIdx.x;
    const int h    = lane >> 4;
    const int j    = lane & 15;

    // bf16 column base: index b*65536 + q*256 + j*16 + k ; uint4 = 8 bf16
    const uint4* base = (const uint4*)(g_Qh + (size_t)b * 65536 + j * 16);
    const int dir = h ? -32 : 32;

    uint4 buf[8][2];
#pragma unroll
    for (int d = 0; d < 8; d++) {
        const int q = h ? (255 - d) : d;
        buf[d][0] = base[q * 32 + 0];
        buf[d][1] = base[q * 32 + 1];
    }
    const uint4* pf = base + (h ? (255 - 8) * 32 : 8 * 32);

    // v = e0 in pingpong 0 (bf16 1.0 = 0x3F80)
    ((unsigned short*)&vsmv[0][h][0])[j] = (j == 0) ? (unsigned short)0x3F80
                                                    : (unsigned short)0;
    __syncwarp();

    unsigned r2 = 0;
    for (int T = 0; T < 128; T += 8) {
#pragma unroll
        for (int s = 0; s < 8; s++) {
            const int t  = T + s;
            const int pp = t & 1;

            // packed v: 8 bf16x2 words (v0..v15)
            const uint4 va = vsmv[pp][h][0];
            const uint4 vb = vsmv[pp][h][1];

            unsigned accA = hmul2(va.x, buf[s][0].x);
            unsigned accB = hmul2(va.y, buf[s][0].y);
            hfma2(accA, va.z, buf[s][0].z);
            hfma2(accB, va.w, buf[s][0].w);
            hfma2(accA, vb.x, buf[s][1].x);
            hfma2(accB, vb.y, buf[s][1].y);
            hfma2(accA, vb.z, buf[s][1].z);
            hfma2(accB, vb.w, buf[s][1].w);

            // prefetch step t+8 into slot s (compile-time index, stays in regs)
            if (t + 8 < 128) {
                buf[s][0] = pf[0];
                buf[s][1] = pf[1];
                pf += dir;
            }

            const unsigned ssum = hadd2(accA, accB);
            const unsigned sw   = __byte_perm(ssum, ssum, 0x1032);
            r2 = hadd2(ssum, sw);    // vp duplicated in both bf16 halves

            ((unsigned short*)&vsmv[pp ^ 1][h][0])[j] = (unsigned short)r2;
            __syncwarp();
        }
    }

    // final column value (bf16 -> fp32)
    const float f = __uint_as_float(r2 << 16);

    float al[16], ar[16];
#pragma unroll
    for (int k = 0; k < 16; k++)
        al[k] = __shfl_sync(0xffffffffu, f, k);
#pragma unroll
    for (int k = 0; k < 16; k++)
        ar[k] = __shfl_sync(0xffffffffu, f, 16 + k);

    if (lane < C_DIM) {
        const float4* Ao = (const float4*)(Aout + lane * 256);
        float acc = 0.f;
#pragma unroll
        for (int l = 0; l < 16; l++) {
            const float a = al[l];
#pragma unroll
            for (int rq = 0; rq < 4; rq++) {
                const float4 xv = Ao[l * 4 + rq];
                acc = fmaf(a * xv.x, ar[rq * 4 + 0], acc);
                acc = fmaf(a * xv.y, ar[rq * 4 + 1], acc);
                acc = fmaf(a * xv.z, ar[rq * 4 + 2], acc);
                acc = fmaf(a * xv.w, ar[rq * 4 + 3], acc);
            }
        }
        out[b * C_DIM + lane] = acc;
    }
}

// ---------------------------------------------------------------------------
extern "C" void kernel_launch(void* const* d_in, const int* in_sizes, int n_in,
                              void* d_out, int out_size)
{
    const float* x      = (const float*)d_in[0];  // (N, B, d)
    const float* tensor = (const float*)d_in[1];  // (N, D, D, d)
    const float* Aout   = (const float*)d_in[2];  // (C, D, D)
    float* out = (float*)d_out;                   // (B, C)

    prq_kernel<<<NQUAD, 256>>>(tensor, x);
    chain_kernel<<<B_DIM, 32>>>(Aout, out);
}

// round 17
// speedup vs baseline: 3.6954x; 3.6954x over previous
#include <cuda_runtime.h>
#include <cuda_bf16.h>

// MPS contraction (R11 structure restored; csh transposed to [g][bl]):
//   prq_kernel : tensor -> pair matrices -> quad combos R (smem) ->
//                per-batch quad matrices Q (bf16, packed f32x2 FMA,
//                coefficients staged in smem as [g][bl] -> LDS.128 reads).
//   chain_kernel: boundary-vector chains in packed bf16 (HFMA2), smem
//                 ping-pong v broadcast, depth-8 register prefetch.
//                 (exact R11/R8 best-measured version)
// N=1024 sites, B=256, D=16, d=2, C=10.

#define NQUAD 256          // quads 0..127 left, 128..255 right (stored transposed)
#define B_DIM 256
#define C_DIM 10

// g_Qh: bf16, index b*65536 + q*256 + j*16 + k  (column j of quad q, k pairs
// packed (k even = low half) by cvt_bf16x2)
__device__ __nv_bfloat16 g_Qh[(size_t)B_DIM * NQUAD * 256]; // 32 MB

// ---- packed helpers --------------------------------------------------------
__device__ __forceinline__ unsigned long long pack2(float lo, float hi) {
    unsigned long long r;
    asm("mov.b64 %0, {%1, %2};" : "=l"(r) : "f"(lo), "f"(hi));
    return r;
}
__device__ __forceinline__ void fma2(unsigned long long& d,
                                     unsigned long long a, unsigned long long b) {
    asm("fma.rn.f32x2 %0, %1, %2, %0;" : "+l"(d) : "l"(a), "l"(b));
}
// u64 (lo = k even, hi = k odd) -> bf16x2 word with k-even in low half
__device__ __forceinline__ unsigned cvt_bf16x2(unsigned long long v) {
    float lo, hi; unsigned p;
    asm("mov.b64 {%0, %1}, %2;" : "=f"(lo), "=f"(hi) : "l"(v));
    asm("cvt.rn.satfinite.bf16x2.f32 %0, %1, %2;" : "=r"(p) : "f"(hi), "f"(lo));
    return p;
}
__device__ __forceinline__ unsigned hmul2(unsigned a, unsigned b) {
    unsigned r;
    asm("mul.rn.bf16x2 %0, %1, %2;" : "=r"(r) : "r"(a), "r"(b));
    return r;
}
__device__ __forceinline__ void hfma2(unsigned& d, unsigned a, unsigned b) {
    asm("fma.rn.bf16x2 %0, %1, %2, %0;" : "+r"(d) : "r"(a), "r"(b));
}
__device__ __forceinline__ unsigned hadd2(unsigned a, unsigned b) {
    unsigned r;
    asm("add.rn.bf16x2 %0, %1, %2;" : "=r"(r) : "r"(a), "r"(b));
    return r;
}

// ---------------------------------------------------------------------------
// K1 (fused): one block per quad q (sites 4q..4q+3), 256 threads, 2 blocks/SM.
// Stage A/B identical to R11. Stage C: 4 slices x 64 batches, acc[4][8]
// (R11 register shape — do NOT force 3 blocks/SM: that spills).
// Coefficient table csh is [g][bl] so a combo's 4 batch coefficients are one
// conflict-free broadcast LDS.128.
// ---------------------------------------------------------------------------
__global__ __launch_bounds__(256, 2)
void prq_kernel(const float* __restrict__ tensor, const float* __restrict__ x)
{
    __shared__ float T[4][1024];                 // 16 KB  [site][l*32 + r*2 + dd]
    __shared__ float SA[4][16 * 17], SB[4][16 * 17];   // 8.5 KB
    __shared__ float Rsh[16 * 288];              // 18 KB, [g][j*18 + k]
    __shared__ float csh[16 * 64];               // 4 KB,  [g][bl]

    // xs aliases T (dead after stage A): [site][batch] float2, 8 KB
    float2* xs = (float2*)&T[0][0];

    const int q = blockIdx.x;
    const int t = threadIdx.x;

    // ---- Stage A: load 4 sites, compute pair matrices ----
    {
        const float4* src = (const float4*)(tensor + (size_t)q * 4096);
        float4* dst = (float4*)&T[0][0];
#pragma unroll
        for (int i = 0; i < 4; i++) dst[t + 256 * i] = src[t + 256 * i];
    }
    __syncthreads();

    const int l = t >> 4;
    const int r = t & 15;
    float pa[4] = {0.f, 0.f, 0.f, 0.f};
    float pb[4] = {0.f, 0.f, 0.f, 0.f};
#pragma unroll
    for (int k = 0; k < 16; k++) {
        const float2 a0 = *(const float2*)&T[0][l * 32 + k * 2];
        const float2 a1 = *(const float2*)&T[1][k * 32 + r * 2];
        pa[0] = fmaf(a0.x, a1.x, pa[0]);
        pa[1] = fmaf(a0.x, a1.y, pa[1]);
        pa[2] = fmaf(a0.y, a1.x, pa[2]);
        pa[3] = fmaf(a0.y, a1.y, pa[3]);
        const float2 b0 = *(const float2*)&T[2][l * 32 + k * 2];
        const float2 b1 = *(const float2*)&T[3][k * 32 + r * 2];
        pb[0] = fmaf(b0.x, b1.x, pb[0]);
        pb[1] = fmaf(b0.x, b1.y, pb[1]);
        pb[2] = fmaf(b0.y, b1.x, pb[2]);
        pb[3] = fmaf(b0.y, b1.y, pb[3]);
    }
    __syncthreads();   // all T reads complete; T becomes xs storage below

    const int idx = (q < 128) ? (l * 17 + r) : (r * 17 + l);   // transpose right side
#pragma unroll
    for (int e = 0; e < 4; e++) { SA[e][idx] = pa[e]; SB[e][idx] = pb[e]; }

    // stage x for ALL 256 batches: 4 sites x 256 batches float2, coalesced
#pragma unroll
    for (int i = 0; i < 4; i++) {
        const int id = t + 256 * i;
        const int s  = id >> 8;
        const int bb = id & 255;
        xs[id] = ((const float2*)x)[(size_t)(4 * q + s) * 256 + bb];
    }
    __syncthreads();

    // ---- Stage B: R columns into padded smem ----
    {
        const int g  = t >> 4;     // combo e*4+f
        const int jj = t & 15;     // output column
        const int e = g >> 2, f = g & 3;
        const float* P1 = (q < 128) ? SA[e] : SB[f];
        const float* P2 = (q < 128) ? SB[f] : SA[e];

        float acc[16];
#pragma unroll
        for (int k = 0; k < 16; k++) acc[k] = 0.f;
#pragma unroll
        for (int m = 0; m < 16; m++) {
            const float bsc = P2[m * 17 + jj];
#pragma unroll
            for (int k = 0; k < 16; k++)
                acc[k] = fmaf(P1[k * 17 + m], bsc, acc[k]);
        }
        float2* dst = (float2*)&Rsh[g * 288 + jj * 18];
#pragma unroll
        for (int kp = 0; kp < 8; kp++)
            dst[kp] = make_float2(acc[2 * kp], acc[2 * kp + 1]);
    }
    __syncthreads();

    // ---- Stage C: 4 slices of 64 batches; coefficients via [g][bl] smem ----
    const int bg = t >> 4;      // 16 groups of 4 batches
    const int j  = t & 15;

#pragma unroll 1
    for (int s8 = 0; s8 < 4; s8++) {
        // compute csh[g][bl]: thread (e = t>>6, bl = t&63) fills g = e*4 + 0..3
        // (4 STS.32 at stride 64 floats: lane-distinct banks, conflict-free)
        {
            const int bl = t & 63;
            const int e  = t >> 6;
            const float2 x0 = xs[0 * 256 + s8 * 64 + bl];
            const float2 x1 = xs[1 * 256 + s8 * 64 + bl];
            const float2 x2 = xs[2 * 256 + s8 * 64 + bl];
            const float2 x3 = xs[3 * 256 + s8 * 64 + bl];
            const float cAe = ((e >> 1) ? x0.y : x0.x) * ((e & 1) ? x1.y : x1.x);
            csh[(e * 4 + 0) * 64 + bl] = cAe * (x2.x * x3.x);
            csh[(e * 4 + 1) * 64 + bl] = cAe * (x2.x * x3.y);
            csh[(e * 4 + 2) * 64 + bl] = cAe * (x2.y * x3.x);
            csh[(e * 4 + 3) * 64 + bl] = cAe * (x2.y * x3.y);
        }
        __syncthreads();

        const int b0 = s8 * 64 + bg * 4;

        unsigned long long acc[4][8];
#pragma unroll
        for (int bb = 0; bb < 4; bb++)
#pragma unroll
            for (int kp = 0; kp < 8; kp++) acc[bb][kp] = 0ull;

#pragma unroll
        for (int g = 0; g < 16; g++) {
            // one broadcast LDS.128: the 4 batch coefficients for this group
            const float4 c4 = *(const float4*)&csh[g * 64 + bg * 4];
            const unsigned long long c0 = pack2(c4.x, c4.x);
            const unsigned long long c1 = pack2(c4.y, c4.y);
            const unsigned long long c2 = pack2(c4.z, c4.z);
            const unsigned long long c3 = pack2(c4.w, c4.w);
            const unsigned long long* Rp =
                (const unsigned long long*)&Rsh[g * 288 + j * 18];
#pragma unroll
            for (int kp = 0; kp < 8; kp++) {
                const unsigned long long rr = Rp[kp];   // conflict-free LDS.64
                fma2(acc[0][kp], c0, rr);
                fma2(acc[1][kp], c1, rr);
                fma2(acc[2][kp], c2, rr);
                fma2(acc[3][kp], c3, rr);
            }
        }

#pragma unroll
        for (int bb = 0; bb < 4; bb++) {
            unsigned w[8];
#pragma unroll
            for (int kp = 0; kp < 8; kp++) w[kp] = cvt_bf16x2(acc[bb][kp]);
            uint4* dst = (uint4*)(g_Qh + (size_t)(b0 + bb) * 65536 + q * 256 + j * 16);
            dst[0] = make_uint4(w[0], w[1], w[2], w[3]);
            dst[1] = make_uint4(w[4], w[5], w[6], w[7]);
        }
        __syncthreads();   // csh reuse by next slice
    }
}

// ---------------------------------------------------------------------------
// K2: chains in packed bf16 (exact R11/R8 best version). grid=256 single-warp
// blocks (one batch each); lanes 0-15 left chain (q ascending), lanes 16-31
// right chain (q descending, transposed quads). Depth-8 register prefetch
// with compile-time slot indices. Per step: 2 LDS.128 (packed v) + 8 HFMA2 +
// 2 HADD2 + PRMT + STS.16 + syncwarp.
// ---------------------------------------------------------------------------
__global__ __launch_bounds__(32)
void chain_kernel(const float* __restrict__ Aout, float* __restrict__ out)
{
    __shared__ uint4 vsmv[2][2][2];   // [pingpong][half][2] = 16 bf16 per half

    const int b    = blockIdx.x;
    const int lane = threadIdx.x;
    const int h    = lane >> 4;
    const int j    = lane & 15;

    // bf16 column base: index b*65536 + q*256 + j*16 + k ; uint4 = 8 bf16
    const uint4* base = (const uint4*)(g_Qh + (size_t)b * 65536 + j * 16);
    const int dir = h ? -32 : 32;

    uint4 buf[8][2];
#pragma unroll
    for (int d = 0; d < 8; d++) {
        const int q = h ? (255 - d) : d;
        buf[d][0] = base[q * 32 + 0];
        buf[d][1] = base[q * 32 + 1];
    }
    const uint4* pf = base + (h ? (255 - 8) * 32 : 8 * 32);

    // v = e0 in pingpong 0 (bf16 1.0 = 0x3F80)
    ((unsigned short*)&vsmv[0][h][0])[j] = (j == 0) ? (unsigned short)0x3F80
                                                    : (unsigned short)0;
    __syncwarp();

    unsigned r2 = 0;
    for (int T = 0; T < 128; T += 8) {
#pragma unroll
        for (int s = 0; s < 8; s++) {
            const int t  = T + s;
            const int pp = t & 1;

            // packed v: 8 bf16x2 words (v0..v15)
            const uint4 va = vsmv[pp][h][0];
            const uint4 vb = vsmv[pp][h][1];

            unsigned accA = hmul2(va.x, buf[s][0].x);
            unsigned accB = hmul2(va.y, buf[s][0].y);
            hfma2(accA, va.z, buf[s][0].z);
            hfma2(accB, va.w, buf[s][0].w);
            hfma2(accA, vb.x, buf[s][1].x);
            hfma2(accB, vb.y, buf[s][1].y);
            hfma2(accA, vb.z, buf[s][1].z);
            hfma2(accB, vb.w, buf[s][1].w);

            // prefetch step t+8 into slot s (compile-time index, stays in regs)
            if (t + 8 < 128) {
                buf[s][0] = pf[0];
                buf[s][1] = pf[1];
                pf += dir;
            }

            const unsigned ssum = hadd2(accA, accB);
            const unsigned sw   = __byte_perm(ssum, ssum, 0x1032);
            r2 = hadd2(ssum, sw);    // vp duplicated in both bf16 halves

            ((unsigned short*)&vsmv[pp ^ 1][h][0])[j] = (unsigned short)r2;
            __syncwarp();
        }
    }

    // final column value (bf16 -> fp32)
    const float f = __uint_as_float(r2 << 16);

    float al[16], ar[16];
#pragma unroll
    for (int k = 0; k < 16; k++)
        al[k] = __shfl_sync(0xffffffffu, f, k);
#pragma unroll
    for (int k = 0; k < 16; k++)
        ar[k] = __shfl_sync(0xffffffffu, f, 16 + k);

    if (lane < C_DIM) {
        const float4* Ao = (const float4*)(Aout + lane * 256);
        float acc = 0.f;
#pragma unroll
        for (int l = 0; l < 16; l++) {
            const float a = al[l];
#pragma unroll
            for (int rq = 0; rq < 4; rq++) {
                const float4 xv = Ao[l * 4 + rq];
                acc = fmaf(a * xv.x, ar[rq * 4 + 0], acc);
                acc = fmaf(a * xv.y, ar[rq * 4 + 1], acc);
                acc = fmaf(a * xv.z, ar[rq * 4 + 2], acc);
                acc = fmaf(a * xv.w, ar[rq * 4 + 3], acc);
            }
        }
        out[b * C_DIM + lane] = acc;
    }
}

// ---------------------------------------------------------------------------
extern "C" void kernel_launch(void* const* d_in, const int* in_sizes, int n_in,
                              void* d_out, int out_size)
{
    const float* x      = (const float*)d_in[0];  // (N, B, d)
    const float* tensor = (const float*)d_in[1];  // (N, D, D, d)
    const float* Aout   = (const float*)d_in[2];  // (C, D, D)
    float* out = (float*)d_out;                   // (B, C)

    prq_kernel<<<NQUAD, 256>>>(tensor, x);
    chain_kernel<<<B_DIM, 32>>>(Aout, out);
}